// round 1
// baseline (speedup 1.0000x reference)
#include <cuda_runtime.h>
#include <math.h>

#define NN 50000
#define NE 800000
#define HD 64

// Scratch (static __device__ arrays — allocation-free per harness rules)
__device__ float4 g_proj4[NN * 32];   // [N, 128] proj for both bases, 25.6 MB
__device__ float4 g_h1a[NN * 16];     // layer-1 hidden, 12.8 MB
__device__ float4 g_h2a[NN * 16];     // layer-2 hidden, 12.8 MB
__device__ float  g_part[512];        // FC partial sums

// ---------------------------------------------------------------------------
// Fused node GEMM: out = x @ [V0 | V1 | loop_w]  (cols 0..127 -> proj,
// cols 128..191 -> h (+bias)). Packed f32x2 FMA, node-pair register tiling.
// Block: 256 threads, 64 nodes, 192 output cols.
// ---------------------------------------------------------------------------
__global__ void __launch_bounds__(256) gemm_kernel(
    const float* __restrict__ x, const float* __restrict__ V2,
    const float* __restrict__ lw, const float* __restrict__ bias,
    float* __restrict__ proj, float* __restrict__ h, int relu_in)
{
    extern __shared__ float sm[];
    float* ws = sm;              // [64][192]
    float* xs = sm + 64 * 192;   // [64][64]  (i-major, node-minor, transposed)
    const int tid = threadIdx.x;
    const int nbase = blockIdx.x * 64;

    // Stage weights: cols 0..127 from V (basis-major), cols 128..191 from loop_w
    for (int idx = tid; idx < 64 * 192; idx += 256) {
        int i = idx / 192, o = idx - i * 192;
        float w = (o < 128) ? V2[((o >> 6) << 12) + (i << 6) + (o & 63)]
                            : lw[(i << 6) + (o - 128)];
        ws[idx] = w;
    }
    // Stage x transposed (apply ReLU of previous layer on read)
    for (int idx = tid; idx < 64 * 64; idx += 256) {
        int nl = idx >> 6, i = idx & 63;
        int n = nbase + nl;
        float v = (n < NN) ? x[(n << 6) + i] : 0.f;
        if (relu_in) v = fmaxf(v, 0.f);
        xs[(i << 6) + nl] = v;
    }
    __syncthreads();

    const int tx = tid & 31;   // col lane: cols tx + 32*c
    const int ty = tid >> 5;   // node group: nodes ty*8 .. ty*8+7 (4 pairs)

    unsigned long long acc[4][6];
#pragma unroll
    for (int p = 0; p < 4; p++)
#pragma unroll
        for (int c = 0; c < 6; c++) acc[p][c] = 0ull;

#pragma unroll 8
    for (int i = 0; i < 64; ++i) {
        unsigned long long wd[6];
#pragma unroll
        for (int c = 0; c < 6; ++c) {
            unsigned int w = __float_as_uint(ws[i * 192 + tx + (c << 5)]);
            asm("mov.b64 %0, {%1, %1};" : "=l"(wd[c]) : "r"(w));
        }
        const unsigned long long* xp =
            (const unsigned long long*)(xs + (i << 6) + (ty << 3));
#pragma unroll
        for (int p = 0; p < 4; ++p) {
            unsigned long long xv = xp[p];
#pragma unroll
            for (int c = 0; c < 6; ++c)
                asm("fma.rn.f32x2 %0, %1, %2, %0;"
                    : "+l"(acc[p][c]) : "l"(xv), "l"(wd[c]));
        }
    }

#pragma unroll
    for (int p = 0; p < 4; ++p) {
        int n0 = nbase + (ty << 3) + (p << 1);
#pragma unroll
        for (int c = 0; c < 6; ++c) {
            int o = tx + (c << 5);
            float2 v = *(float2*)&acc[p][c];   // .x -> node n0, .y -> node n0+1
            if (o < 128) {
                if (n0 < NN)     proj[(n0 << 7) + o]       = v.x;
                if (n0 + 1 < NN) proj[((n0 + 1) << 7) + o] = v.y;
            } else {
                float b = bias[o - 128];
                if (n0 < NN)     h[(n0 << 6) + o - 128]       = v.x + b;
                if (n0 + 1 < NN) h[((n0 + 1) << 6) + o - 128] = v.y + b;
            }
        }
    }
}

// ---------------------------------------------------------------------------
// Edge scatter: half-warp per edge. msg = c0*proj[s,0,:] + c1*proj[s,1,:];
// h[dst] += msg via red.global.add.v4.f32 (16 lanes x float4 = 64 floats).
// ---------------------------------------------------------------------------
__global__ void __launch_bounds__(256) edge_kernel(
    const float4* __restrict__ proj, const int* __restrict__ src,
    const int* __restrict__ dst, const int* __restrict__ et,
    const float* __restrict__ comp_l, float4* __restrict__ h)
{
    int gid = blockIdx.x * 256 + threadIdx.x;
    int e = gid >> 4;
    if (e >= NE) return;
    int sub = gid & 15;
    int s = __ldg(src + e);
    int d = __ldg(dst + e);
    int t = __ldg(et + e);
    float c0 = __ldg(comp_l + t * 2);
    float c1 = __ldg(comp_l + t * 2 + 1);
    float4 p0 = proj[s * 32 + sub];        // basis 0
    float4 p1 = proj[s * 32 + 16 + sub];   // basis 1
    float4 m;
    m.x = c0 * p0.x + c1 * p1.x;
    m.y = c0 * p0.y + c1 * p1.y;
    m.z = c0 * p0.z + c1 * p1.z;
    m.w = c0 * p0.w + c1 * p1.w;
    float4* addr = h + d * 16 + sub;
    asm volatile("red.global.add.v4.f32 [%0], {%1,%2,%3,%4};"
                 :: "l"(addr), "f"(m.x), "f"(m.y), "f"(m.z), "f"(m.w)
                 : "memory");
}

// ---------------------------------------------------------------------------
// FC readout: two-stage deterministic reduction + sigmoid
// ---------------------------------------------------------------------------
__global__ void __launch_bounds__(256) fc_partial(
    const float4* __restrict__ a, const float4* __restrict__ w)
{
    int tid = blockIdx.x * 256 + threadIdx.x;
    float s = 0.f;
    for (int i = tid; i < NN * 16; i += 512 * 256) {
        float4 xa = a[i], xw = w[i];
        s += xa.x * xw.x + xa.y * xw.y + xa.z * xw.z + xa.w * xw.w;
    }
    __shared__ float red[256];
    red[threadIdx.x] = s;
    __syncthreads();
    for (int st = 128; st > 0; st >>= 1) {
        if (threadIdx.x < st) red[threadIdx.x] += red[threadIdx.x + st];
        __syncthreads();
    }
    if (threadIdx.x == 0) g_part[blockIdx.x] = red[0];
}

__global__ void fc_final(const float* __restrict__ fc_b, float* __restrict__ out)
{
    __shared__ float red[512];
    red[threadIdx.x] = g_part[threadIdx.x];
    __syncthreads();
    for (int st = 256; st > 0; st >>= 1) {
        if (threadIdx.x < st) red[threadIdx.x] += red[threadIdx.x + st];
        __syncthreads();
    }
    if (threadIdx.x == 0) out[0] = 1.f / (1.f + expf(-(red[0] + fc_b[0])));
}

// ---------------------------------------------------------------------------
extern "C" void kernel_launch(void* const* d_in, const int* in_sizes, int n_in,
                              void* d_out, int out_size)
{
    const float* features = (const float*)d_in[0];
    const float* V        = (const float*)d_in[1];   // [2,2,64,64]
    const float* comp     = (const float*)d_in[2];   // [2,8,2]
    const float* loop_w   = (const float*)d_in[3];   // [2,64,64]
    const float* bias     = (const float*)d_in[4];   // [2,64]
    const float* fc_w     = (const float*)d_in[5];   // [1, N*64]
    const float* fc_b     = (const float*)d_in[6];   // [1]
    const int*   src      = (const int*)d_in[7];
    const int*   dst      = (const int*)d_in[8];
    const int*   et       = (const int*)d_in[9];
    float* out = (float*)d_out;

    void *p_proj, *p_h1, *p_h2;
    cudaGetSymbolAddress(&p_proj, g_proj4);
    cudaGetSymbolAddress(&p_h1, g_h1a);
    cudaGetSymbolAddress(&p_h2, g_h2a);

    const int smem = 64 * 192 * 4 + 64 * 64 * 4;  // 65536 B
    cudaFuncSetAttribute(gemm_kernel,
                         cudaFuncAttributeMaxDynamicSharedMemorySize, smem);

    const int gemm_blocks = (NN + 63) / 64;        // 782
    const int edge_blocks = (NE * 16) / 256;       // 50000

    // Layer 0
    gemm_kernel<<<gemm_blocks, 256, smem>>>(features, V, loop_w, bias,
                                            (float*)p_proj, (float*)p_h1, 0);
    edge_kernel<<<edge_blocks, 256>>>((const float4*)p_proj, src, dst, et,
                                      comp, (float4*)p_h1);
    // Layer 1 (ReLU applied on read of h1)
    gemm_kernel<<<gemm_blocks, 256, smem>>>((const float*)p_h1, V + 8192,
                                            loop_w + 4096, bias + 64,
                                            (float*)p_proj, (float*)p_h2, 1);
    edge_kernel<<<edge_blocks, 256>>>((const float4*)p_proj, src, dst, et,
                                      comp + 16, (float4*)p_h2);
    // FC readout
    fc_partial<<<512, 256>>>((const float4*)p_h2, (const float4*)fc_w);
    fc_final<<<1, 512>>>(fc_b, out);
}

// round 2
// speedup vs baseline: 1.1198x; 1.1198x over previous
#include <cuda_runtime.h>
#include <cuda_fp16.h>
#include <math.h>

#define NN 50000
#define NE 800000
#define HD 64
#define XS_STRIDE 66

// ---------------- scratch (static __device__, allocation-free) ----------------
__device__ uint2  g_projh[NN * 32];     // [N,128] fp16 proj (both bases), 12.8 MB
__device__ float4 g_h1a[NN * 16];       // layer-1 hidden fp32, 12.8 MB
__device__ float4 g_h2a[NN * 16];       // layer-2 hidden fp32, 12.8 MB
__device__ int    g_deg[NN];
__device__ int    g_offs[NN + 1];
__device__ int    g_cursor[NN];
__device__ int    g_tsum[128];
__device__ int    g_csr[NE];            // packed src | (etype<<17)
__device__ float  g_part[512];

// ---------------- CSR build: zero / hist / scan / scatter ----------------
__global__ void __launch_bounds__(256) zero_kernel(int* deg, int* cursor)
{
    int i = blockIdx.x * 256 + threadIdx.x;
    if (i < NN) { deg[i] = 0; cursor[i] = 0; }
}

__global__ void __launch_bounds__(256) hist_kernel(const int* __restrict__ dst,
                                                   int* __restrict__ deg)
{
    int e = blockIdx.x * 256 + threadIdx.x;
    if (e < NE) atomicAdd(&deg[dst[e]], 1);
}

__global__ void __launch_bounds__(512) scan1_kernel(const int* __restrict__ deg,
                                                    int* __restrict__ offs,
                                                    int* __restrict__ tsum)
{
    __shared__ int s[512];
    int t = threadIdx.x;
    int g = blockIdx.x * 512 + t;
    int v = (g < NN) ? deg[g] : 0;
    s[t] = v;
    __syncthreads();
    for (int d = 1; d < 512; d <<= 1) {
        int x = (t >= d) ? s[t - d] : 0;
        __syncthreads();
        s[t] += x;
        __syncthreads();
    }
    if (g < NN) offs[g] = s[t] - v;            // exclusive within tile
    if (t == 511) tsum[blockIdx.x] = s[511];   // tile total
}

__global__ void __launch_bounds__(128) scan2_kernel(int* __restrict__ tsum, int ntiles)
{
    __shared__ int s[128];
    int t = threadIdx.x;
    int v = (t < ntiles) ? tsum[t] : 0;
    s[t] = v;
    __syncthreads();
    for (int d = 1; d < 128; d <<= 1) {
        int x = (t >= d) ? s[t - d] : 0;
        __syncthreads();
        s[t] += x;
        __syncthreads();
    }
    if (t < ntiles) tsum[t] = s[t] - v;        // exclusive tile prefixes
}

__global__ void __launch_bounds__(256) scan3_kernel(int* __restrict__ offs,
                                                    const int* __restrict__ tsum)
{
    int i = blockIdx.x * 256 + threadIdx.x;
    if (i < NN)       offs[i] += tsum[i >> 9];
    else if (i == NN) offs[NN] = NE;
}

__global__ void __launch_bounds__(256) scatter_kernel(
    const int* __restrict__ src, const int* __restrict__ dst,
    const int* __restrict__ et, const int* __restrict__ offs,
    int* __restrict__ cursor, int* __restrict__ csr)
{
    int e = blockIdx.x * 256 + threadIdx.x;
    if (e >= NE) return;
    int d = dst[e];
    int pos = offs[d] + atomicAdd(&cursor[d], 1);
    csr[pos] = src[e] | (et[e] << 17);
}

// ---------------------------------------------------------------------------
// Fused node GEMM: [V0|V1|loop_w], 64 nodes/CTA, 128 threads, 8 node-pairs
// per thread via packed f32x2 FMA. proj written as fp16, h as fp32 (+bias).
// ---------------------------------------------------------------------------
__global__ void __launch_bounds__(128) gemm_kernel(
    const float* __restrict__ x, const float* __restrict__ V2,
    const float* __restrict__ lw, const float* __restrict__ bias,
    __half* __restrict__ projh, float* __restrict__ h, int relu_in)
{
    extern __shared__ float sm[];
    float* ws = sm;                   // [64][192]
    float* xs = sm + 64 * 192;        // [64][XS_STRIDE] (i-major, node-minor)
    const int tid = threadIdx.x;
    const int nbase = blockIdx.x * 64;

    for (int idx = tid; idx < 64 * 192; idx += 128) {
        int i = idx / 192, o = idx - i * 192;
        ws[idx] = (o < 128) ? V2[((o >> 6) << 12) + (i << 6) + (o & 63)]
                            : lw[(i << 6) + (o - 128)];
    }
    for (int idx = tid; idx < 64 * 64; idx += 128) {
        int nl = idx >> 6, i = idx & 63;
        int n = nbase + nl;
        float v = (n < NN) ? x[(size_t)(n << 6) + i] : 0.f;
        if (relu_in) v = fmaxf(v, 0.f);
        xs[i * XS_STRIDE + nl] = v;
    }
    __syncthreads();

    const int tx = tid & 31;    // col lane: cols tx + 32*c
    const int ty = tid >> 5;    // node group: nodes ty*16 .. ty*16+15 (8 pairs)

    unsigned long long acc[8][6];
#pragma unroll
    for (int p = 0; p < 8; ++p)
#pragma unroll
        for (int c = 0; c < 6; ++c) acc[p][c] = 0ull;

#pragma unroll 4
    for (int i = 0; i < 64; ++i) {
        unsigned long long wd[6];
#pragma unroll
        for (int c = 0; c < 6; ++c) {
            unsigned int w = __float_as_uint(ws[i * 192 + tx + (c << 5)]);
            asm("mov.b64 %0, {%1, %1};" : "=l"(wd[c]) : "r"(w));
        }
        const float* xrow = xs + i * XS_STRIDE + (ty << 4);
#pragma unroll
        for (int p = 0; p < 8; ++p) {
            unsigned long long xv = *(const unsigned long long*)(xrow + 2 * p);
#pragma unroll
            for (int c = 0; c < 6; ++c)
                asm("fma.rn.f32x2 %0, %1, %2, %0;"
                    : "+l"(acc[p][c]) : "l"(xv), "l"(wd[c]));
        }
    }

#pragma unroll
    for (int p = 0; p < 8; ++p) {
        int n0 = nbase + (ty << 4) + (p << 1);
        bool v0 = (n0 < NN), v1 = (n0 + 1 < NN);
#pragma unroll
        for (int c = 0; c < 6; ++c) {
            int o = tx + (c << 5);
            float2 v = *(float2*)&acc[p][c];
            if (o < 128) {
                if (v0) projh[(size_t)n0 * 128 + o]       = __float2half_rn(v.x);
                if (v1) projh[(size_t)(n0 + 1) * 128 + o] = __float2half_rn(v.y);
            } else {
                float b = bias[o - 128];
                if (v0) h[(size_t)n0 * 64 + (o - 128)]       = v.x + b;
                if (v1) h[(size_t)(n0 + 1) * 64 + (o - 128)] = v.y + b;
            }
        }
    }
}

// ---------------------------------------------------------------------------
// Aggregation: half-warp per dst node; walks its sorted in-edge list,
// gathers fp16 proj, mixes basis coefficients, single fp32 h[dst] += acc.
// ---------------------------------------------------------------------------
__global__ void __launch_bounds__(256) agg_kernel(
    const uint2* __restrict__ projh, const int* __restrict__ offs,
    const int* __restrict__ csr, const float* __restrict__ comp_l,
    float4* __restrict__ h)
{
    __shared__ float scomp[16];
    if (threadIdx.x < 16) scomp[threadIdx.x] = comp_l[threadIdx.x];
    __syncthreads();

    int gid = blockIdx.x * 256 + threadIdx.x;
    int n = gid >> 4;
    if (n >= NN) return;
    int sub = gid & 15;
    int beg = offs[n], end = offs[n + 1];
    unsigned mask = 0xFFFFu << (threadIdx.x & 16);

    float4 acc = make_float4(0.f, 0.f, 0.f, 0.f);
    for (int j = beg; j < end; j += 16) {
        int p = 0;
        if (j + sub < end) p = __ldg(csr + j + sub);
        int cnt = min(16, end - j);
        for (int k = 0; k < cnt; ++k) {
            int pk = __shfl_sync(mask, p, k, 16);
            int s = pk & 0x1FFFF;
            int t = pk >> 17;
            uint2 a0 = __ldg(projh + (size_t)s * 32 + sub);        // basis 0
            uint2 a1 = __ldg(projh + (size_t)s * 32 + 16 + sub);   // basis 1
            float c0 = scomp[2 * t], c1 = scomp[2 * t + 1];
            float2 f0a = __half22float2(*(__half2*)&a0.x);
            float2 f0b = __half22float2(*(__half2*)&a0.y);
            float2 f1a = __half22float2(*(__half2*)&a1.x);
            float2 f1b = __half22float2(*(__half2*)&a1.y);
            acc.x = fmaf(c0, f0a.x, fmaf(c1, f1a.x, acc.x));
            acc.y = fmaf(c0, f0a.y, fmaf(c1, f1a.y, acc.y));
            acc.z = fmaf(c0, f0b.x, fmaf(c1, f1b.x, acc.z));
            acc.w = fmaf(c0, f0b.y, fmaf(c1, f1b.y, acc.w));
        }
    }
    float4* hp = h + (size_t)n * 16 + sub;
    float4 old = *hp;
    old.x += acc.x; old.y += acc.y; old.z += acc.z; old.w += acc.w;
    *hp = old;
}

// ---------------------------------------------------------------------------
// FC readout: two-stage deterministic reduction + sigmoid
// ---------------------------------------------------------------------------
__global__ void __launch_bounds__(256) fc_partial(
    const float4* __restrict__ a, const float4* __restrict__ w)
{
    int tid = blockIdx.x * 256 + threadIdx.x;
    float s = 0.f;
    for (int i = tid; i < NN * 16; i += 512 * 256) {
        float4 xa = a[i], xw = w[i];
        s += xa.x * xw.x + xa.y * xw.y + xa.z * xw.z + xa.w * xw.w;
    }
    __shared__ float red[256];
    red[threadIdx.x] = s;
    __syncthreads();
    for (int st = 128; st > 0; st >>= 1) {
        if (threadIdx.x < st) red[threadIdx.x] += red[threadIdx.x + st];
        __syncthreads();
    }
    if (threadIdx.x == 0) g_part[blockIdx.x] = red[0];
}

__global__ void fc_final(const float* __restrict__ fc_b, float* __restrict__ out)
{
    __shared__ float red[512];
    red[threadIdx.x] = g_part[threadIdx.x];
    __syncthreads();
    for (int st = 256; st > 0; st >>= 1) {
        if (threadIdx.x < st) red[threadIdx.x] += red[threadIdx.x + st];
        __syncthreads();
    }
    if (threadIdx.x == 0) out[0] = 1.f / (1.f + expf(-(red[0] + fc_b[0])));
}

// ---------------------------------------------------------------------------
extern "C" void kernel_launch(void* const* d_in, const int* in_sizes, int n_in,
                              void* d_out, int out_size)
{
    const float* features = (const float*)d_in[0];
    const float* V        = (const float*)d_in[1];   // [2,2,64,64]
    const float* comp     = (const float*)d_in[2];   // [2,8,2]
    const float* loop_w   = (const float*)d_in[3];   // [2,64,64]
    const float* bias     = (const float*)d_in[4];   // [2,64]
    const float* fc_w     = (const float*)d_in[5];   // [1, N*64]
    const float* fc_b     = (const float*)d_in[6];   // [1]
    const int*   src      = (const int*)d_in[7];
    const int*   dst      = (const int*)d_in[8];
    const int*   et       = (const int*)d_in[9];
    float* out = (float*)d_out;

    void *p_projh, *p_h1, *p_h2, *p_deg, *p_offs, *p_cur, *p_tsum, *p_csr;
    cudaGetSymbolAddress(&p_projh, g_projh);
    cudaGetSymbolAddress(&p_h1, g_h1a);
    cudaGetSymbolAddress(&p_h2, g_h2a);
    cudaGetSymbolAddress(&p_deg, g_deg);
    cudaGetSymbolAddress(&p_offs, g_offs);
    cudaGetSymbolAddress(&p_cur, g_cursor);
    cudaGetSymbolAddress(&p_tsum, g_tsum);
    cudaGetSymbolAddress(&p_csr, g_csr);

    const int smem = 64 * 192 * 4 + 64 * XS_STRIDE * 4;   // 66048 B
    cudaFuncSetAttribute(gemm_kernel,
                         cudaFuncAttributeMaxDynamicSharedMemorySize, smem);

    const int ntiles      = (NN + 511) / 512;             // 98
    const int node_blocks = (NN + 255) / 256;             // 196
    const int edge_blocks = (NE + 255) / 256;             // 3125
    const int gemm_blocks = (NN + 63) / 64;               // 782
    const int agg_blocks  = (NN * 16) / 256;              // 3125

    // --- CSR build (once, shared by both layers) ---
    zero_kernel<<<node_blocks, 256>>>((int*)p_deg, (int*)p_cur);
    hist_kernel<<<edge_blocks, 256>>>(dst, (int*)p_deg);
    scan1_kernel<<<ntiles, 512>>>((int*)p_deg, (int*)p_offs, (int*)p_tsum);
    scan2_kernel<<<1, 128>>>((int*)p_tsum, ntiles);
    scan3_kernel<<<(NN + 256) / 256, 256>>>((int*)p_offs, (int*)p_tsum);
    scatter_kernel<<<edge_blocks, 256>>>(src, dst, et, (int*)p_offs,
                                         (int*)p_cur, (int*)p_csr);

    // --- Layer 0 ---
    gemm_kernel<<<gemm_blocks, 128, smem>>>(features, V, loop_w, bias,
                                            (__half*)p_projh, (float*)p_h1, 0);
    agg_kernel<<<agg_blocks, 256>>>((const uint2*)p_projh, (const int*)p_offs,
                                    (const int*)p_csr, comp, (float4*)p_h1);
    // --- Layer 1 (ReLU applied on read of h1) ---
    gemm_kernel<<<gemm_blocks, 128, smem>>>((const float*)p_h1, V + 8192,
                                            loop_w + 4096, bias + 64,
                                            (__half*)p_projh, (float*)p_h2, 1);
    agg_kernel<<<agg_blocks, 256>>>((const uint2*)p_projh, (const int*)p_offs,
                                    (const int*)p_csr, comp + 16, (float4*)p_h2);
    // --- FC readout ---
    fc_partial<<<512, 256>>>((const float4*)p_h2, (const float4*)fc_w);
    fc_final<<<1, 512>>>(fc_b, out);
}